// round 16
// baseline (speedup 1.0000x reference)
#include <cuda_runtime.h>
#include <math.h>

#define TSTEPS 501
#define BATCH  32
#define TENC   512
#define DENC   512
#define NMEL   160
#define PRE    256
#define HDIM   1024
#define KA     1792
#define KD     2560
#define NB     128
#define NT     256

// ---------------- static device scratch ----------------
__device__ float g_wAT[KA * 4096];     // k-major, gate-interleaved cols (cell*4+gate)
__device__ float g_wDT[KD * 4096];
__device__ float g_bA[4096], g_bD[4096];          // remapped bias
__device__ float g_wqT[HDIM * 128];               // [k][j]
__device__ float g_wlp[32 * 128];                 // [c][j]
__device__ float g_wmT[384 * 176 * 4];            // [k/4][j(176)][4k]
__device__ float g_bmp[176];
__device__ float g_tmp[TSTEPS * BATCH * PRE];
__device__ float g_pre[TSTEPS * PRE * BATCH];     // [t][k][b]
__device__ float g_keys[BATCH * TENC * 128];
__device__ float g_loc [BATCH * TENC * 128];
__device__ float g_ctx[DENC * BATCH];             // [d][b]
__device__ float g_ah[2][HDIM * BATCH];           // [cell][b]
__device__ float g_ac[2][HDIM * BATCH];
__device__ float g_dh[2][HDIM * BATCH];
__device__ float g_dc[2][HDIM * BATCH];
__device__ float g_aw [BATCH * TENC], g_awt[BATCH * TENC];
__device__ unsigned g_cnt = 0;
__device__ volatile unsigned g_gen = 0;

union Smem {
    float tr[32][33];
    struct { float x[16][NMEL]; } p1;
    struct { float x[16][PRE]; } p2;
    struct { float x[8][DENC]; } ke;
    struct { float xs[2048]; } ls;                      // [kk][b]
    struct { float aw[512], awt[512], slc[128][33]; } cv;
    struct { float sah[1024], sq[128], swa[128], qp[256], e[512], sp[512], red[256]; } at;
    struct { float sh[1536]; } op;
};

__device__ __forceinline__ void gsync() {
    __threadfence();
    __syncthreads();
    if (threadIdx.x == 0) {
        unsigned gen = g_gen;
        if (atomicAdd(&g_cnt, 1u) == NB - 1u) { g_cnt = 0u; __threadfence(); g_gen = gen + 1u; }
        else { while (g_gen == gen) __nanosleep(64); }
    }
    __syncthreads();
    __threadfence();
}

// accurate fast tanh: 1 - 2/(e^{2x}+1); rel err ~1e-6 (vs 1e-3 for tanh.approx)
__device__ __forceinline__ float tnh(float x) {
    float e = __expf(2.f * x);
    return 1.f - __fdividef(2.f, e + 1.f);
}
__device__ __forceinline__ float sigf(float x) { return 1.f / (1.f + expf(-x)); }

// transpose src[4096][C] -> dst[(rowOff+c)*4096 + remap(r)], remap(r)=(r&1023)*4+(r>>10)
__device__ void tpose(Smem& s, float* dst, const float* __restrict__ src,
                      int C, int rowOff, int bi, int tid) {
    int x = tid & 31, y = tid >> 5;
    int ntile = (C >> 5) * 128;
    for (int idx = bi; idx < ntile; idx += NB) {
        int rt = idx & 127, ct = idx >> 7;
        __syncthreads();
#pragma unroll
        for (int i = 0; i < 4; i++)
            s.tr[y + i * 8][x] = src[(size_t)(rt * 32 + y + i * 8) * C + ct * 32 + x];
        __syncthreads();
        int g = (rt * 32) >> 10, rb = ((rt * 32) & 1023) * 4 + g;
#pragma unroll
        for (int i = 0; i < 4; i++) {
            int c = ct * 32 + y + i * 8;
            dst[(size_t)(rowOff + c) * 4096 + rb + x * 4] = s.tr[x][y + i * 8];
        }
    }
    __syncthreads();
}

// ---------------- fused LSTM: warp = 1 cell x 32 batch lanes ----------------
template <int MODE>
__device__ void lstm(Smem& s, int t, int bi, int tid) {
    const int p = t & 1, n = p ^ 1;
    constexpr int K = MODE ? KD : KA;
    const float* wT    = MODE ? g_wDT : g_wAT;
    const float* bias  = MODE ? g_bD  : g_bA;
    const float* cprev = MODE ? g_dc[p] : g_ac[p];
    float* co = MODE ? g_dc[n] : g_ac[n];
    float* ho = MODE ? g_dh[n] : g_ah[n];
    const float* ahr = MODE ? g_ah[n] : g_ah[p];
    const float* dhr = g_dh[p];
    const float* pret = g_pre + (size_t)t * PRE * BATCH;

    int lane = tid & 31, w = tid >> 5;
    int cell = bi * 8 + w;
    float4 bs = *(const float4*)&bias[cell * 4];
    unsigned long long a01, a23;
    asm("mov.b64 %0,{%1,%2};" : "=l"(a01) : "f"(bs.x), "f"(bs.y));
    asm("mov.b64 %0,{%1,%2};" : "=l"(a23) : "f"(bs.z), "f"(bs.w));

    for (int kt = 0; kt < K / 64; kt++) {
        __syncthreads();
#pragma unroll
        for (int i = 0; i < 8; i++) {
            int idx = i * NT + tid;
            int kk = idx >> 5, b = idx & 31;
            int kg = kt * 64 + kk;
            float v;
            if (MODE == 0)
                v = kg < 256 ? pret[kg * 32 + b]
                  : (kg < 768 ? __ldcg(&g_ctx[(kg - 256) * 32 + b])
                              : __ldcg(&ahr[(kg - 768) * 32 + b]));
            else
                v = kg < 512 ? __ldcg(&g_ctx[kg * 32 + b])
                  : (kg < 1536 ? __ldcg(&ahr[(kg - 512) * 32 + b])
                               : __ldcg(&dhr[(kg - 1536) * 32 + b]));
            s.ls.xs[idx] = v;
        }
        __syncthreads();
        const float* wb = wT + (size_t)(kt * 64) * 4096 + cell * 4;
#pragma unroll 8
        for (int kk = 0; kk < 64; kk++) {
            ulonglong2 wv = __ldg((const ulonglong2*)(wb + (size_t)kk * 4096));
            float x = s.ls.xs[kk * 32 + lane];
            unsigned long long x2;
            asm("mov.b64 %0,{%1,%1};" : "=l"(x2) : "f"(x));
            asm("fma.rn.f32x2 %0,%1,%2,%0;" : "+l"(a01) : "l"(wv.x), "l"(x2));
            asm("fma.rn.f32x2 %0,%1,%2,%0;" : "+l"(a23) : "l"(wv.y), "l"(x2));
        }
    }
    float gi, gf, gg, go;
    asm("mov.b64 {%0,%1},%2;" : "=f"(gi), "=f"(gf) : "l"(a01));
    asm("mov.b64 {%0,%1},%2;" : "=f"(gg), "=f"(go) : "l"(a23));
    float cp = cprev[cell * 32 + lane];
    float cn = sigf(gf) * cp + sigf(gi) * tanhf(gg);
    co[cell * 32 + lane] = cn;
    ho[cell * 32 + lane] = sigf(go) * tanhf(cn);
    __syncthreads();
}

// ---------------- location conv + projection ----------------
__device__ void conv(Smem& s, int bi, int tid, const float* __restrict__ cw,
                     const float* __restrict__ cb, const float* __restrict__ bl) {
    int b = bi >> 2, t0 = (bi & 3) * 128;
    __syncthreads();
    for (int i = tid; i < 512; i += NT) {
        s.cv.aw[i]  = __ldcg(&g_aw[b * 512 + i]);
        s.cv.awt[i] = __ldcg(&g_awt[b * 512 + i]);
    }
    __syncthreads();
    if (tid < 128) {
        int tg = t0 + tid;
        float lc[32];
#pragma unroll
        for (int c = 0; c < 32; c++) lc[c] = __ldg(&cb[c]);
        for (int k = 0; k < 31; k++) {
            int tt = tg - 15 + k;
            if (tt >= 0 && tt < 512) {
                float av = s.cv.aw[tt], wv = s.cv.awt[tt];
#pragma unroll
                for (int c = 0; c < 32; c++)
                    lc[c] += __ldg(&cw[c * 62 + k]) * av + __ldg(&cw[c * 62 + 31 + k]) * wv;
            }
        }
#pragma unroll
        for (int c = 0; c < 32; c++) s.cv.slc[tid][c] = lc[c];
    }
    __syncthreads();
    int j = tid & 127, th = tid >> 7;
    float wreg[32];
#pragma unroll
    for (int c = 0; c < 32; c++) wreg[c] = __ldg(&g_wlp[c * 128 + j]);
    float blv = __ldg(&bl[j]);
    for (int ti = 0; ti < 64; ti++) {
        int tl = th * 64 + ti;
        float acc = blv;
#pragma unroll
        for (int c = 0; c < 32; c++) acc += wreg[c] * s.cv.slc[tl][c];
        g_loc[((size_t)(b * 512 + t0 + tl)) * 128 + j] = acc;
    }
    __syncthreads();
}

// ---------------- output projection for step 'to' ----------------
__device__ void outproj(Smem& s, int to, int b, const float* __restrict__ dhp,
                        float* __restrict__ outM, float* __restrict__ outG) {
    int tid = threadIdx.x;
    __syncthreads();
    for (int i = tid; i < 1536; i += NT)
        s.op.sh[i] = (i < 1024) ? __ldcg(&dhp[i * 32 + b]) : __ldcg(&g_ctx[(i - 1024) * 32 + b]);
    __syncthreads();
    if (tid < 176) {
        float acc = g_bmp[tid];
        for (int k4 = 0; k4 < 384; k4++) {
            float4 w = *(const float4*)&g_wmT[(size_t)k4 * 704 + tid * 4];
            float4 x = *(const float4*)&s.op.sh[k4 * 4];
            acc += w.x * x.x + w.y * x.y + w.z * x.z + w.w * x.w;
        }
        if (tid < 160) outM[((size_t)to * BATCH + b) * NMEL + tid] = acc;
        else if (tid == 160) outG[(size_t)to * BATCH + b] = acc;
    }
    __syncthreads();
}

// ---------------- attention ----------------
__device__ void attn(Smem& s, int t, int b, int tid, const float* __restrict__ enc,
                     const float* __restrict__ bq, const float* __restrict__ wa,
                     const float* __restrict__ ba, const unsigned char* __restrict__ mask,
                     float* __restrict__ outA) {
    const int n = (t & 1) ^ 1;
    __syncthreads();
    for (int i = tid; i < 1024; i += NT) s.at.sah[i] = __ldcg(&g_ah[n][i * 32 + b]);
    if (tid < 128) s.at.swa[tid] = __ldg(&wa[tid]);
    __syncthreads();
    {
        int j = tid & 127, h = tid >> 7;
        float acc = 0.f;
        const float* wr = &g_wqT[(size_t)(h * 512) * 128 + j];
        const float* xr = &s.at.sah[h * 512];
#pragma unroll 8
        for (int k = 0; k < 512; k++) acc += __ldg(wr + (size_t)k * 128) * xr[k];
        s.at.qp[tid] = acc;
    }
    __syncthreads();
    if (tid < 128) s.at.sq[tid] = __ldg(&bq[tid]) + s.at.qp[tid] + s.at.qp[tid + 128];
    __syncthreads();

    float bav = __ldg(&ba[0]);
#pragma unroll
    for (int i = 0; i < 2; i++) {
        int tt = i * 256 + tid;
        const float4* kp = (const float4*)&g_keys[(size_t)(b * 512 + tt) * 128];
        const float4* lp = (const float4*)&g_loc [(size_t)(b * 512 + tt) * 128];
        float ee = bav;
#pragma unroll 4
        for (int j4 = 0; j4 < 32; j4++) {
            float4 q = *(const float4*)&s.at.sq[j4 * 4];
            float4 w = *(const float4*)&s.at.swa[j4 * 4];
            float4 kv = __ldcg(&kp[j4]);
            float4 lv = __ldcg(&lp[j4]);
            ee += w.x * tnh(q.x + kv.x + lv.x) + w.y * tnh(q.y + kv.y + lv.y)
                + w.z * tnh(q.z + kv.z + lv.z) + w.w * tnh(q.w + kv.w + lv.w);
        }
        if (mask[b * 512 + tt]) ee = -INFINITY;
        s.at.e[tt] = ee;
    }
    __syncthreads();
    s.at.red[tid] = fmaxf(s.at.e[tid], s.at.e[256 + tid]);
    __syncthreads();
    for (int st = 128; st > 0; st >>= 1) {
        if (tid < st) s.at.red[tid] = fmaxf(s.at.red[tid], s.at.red[tid + st]);
        __syncthreads();
    }
    float mx = s.at.red[0];
    __syncthreads();
    float ls = 0.f;
#pragma unroll
    for (int i = 0; i < 2; i++) {
        int tt = i * 256 + tid;
        float pv = expf(s.at.e[tt] - mx);
        s.at.sp[tt] = pv; ls += pv;
    }
    s.at.red[tid] = ls;
    __syncthreads();
    for (int st = 128; st > 0; st >>= 1) {
        if (tid < st) s.at.red[tid] += s.at.red[tid + st];
        __syncthreads();
    }
    float inv = 1.f / s.at.red[0];
    __syncthreads();
#pragma unroll
    for (int i = 0; i < 2; i++) {
        int tt = i * 256 + tid;
        float pv = s.at.sp[tt] * inv;
        s.at.sp[tt] = pv;
        g_aw[b * 512 + tt] = pv;
        g_awt[b * 512 + tt] += pv;
        outA[((size_t)t * BATCH + b) * 512 + tt] = pv;
    }
    __syncthreads();
#pragma unroll
    for (int i = 0; i < 2; i++) {
        int d = i * 256 + tid;
        const float* eb = enc + (size_t)b * 512 * 512 + d;
        float acc = 0.f;
#pragma unroll 8
        for (int tt = 0; tt < 512; tt++) acc += s.at.sp[tt] * __ldg(eb + (size_t)tt * 512);
        g_ctx[d * 32 + b] = acc;
    }
    __syncthreads();
}

// ---------------- the single persistent kernel ----------------
__global__ void __launch_bounds__(NT, 1) mega(
    const float* __restrict__ enc, const float* __restrict__ mels,
    const unsigned char* __restrict__ mask,
    const float* __restrict__ w_pre1, const float* __restrict__ b_pre1,
    const float* __restrict__ w_pre2, const float* __restrict__ b_pre2,
    const float* __restrict__ wih_a, const float* __restrict__ whh_a,
    const float* __restrict__ bih_a, const float* __restrict__ bhh_a,
    const float* __restrict__ wq, const float* __restrict__ bq,
    const float* __restrict__ wk, const float* __restrict__ bk,
    const float* __restrict__ cw, const float* __restrict__ cb,
    const float* __restrict__ wl, const float* __restrict__ bl,
    const float* __restrict__ wa, const float* __restrict__ ba,
    const float* __restrict__ wih_d, const float* __restrict__ whh_d,
    const float* __restrict__ bih_d, const float* __restrict__ bhh_d,
    const float* __restrict__ wm, const float* __restrict__ bm,
    const float* __restrict__ wg, const float* __restrict__ bg,
    float* __restrict__ outM, float* __restrict__ outG, float* __restrict__ outA)
{
    __shared__ Smem s;
    int bi = blockIdx.x, tid = threadIdx.x;
    int gid = bi * NT + tid, gn = NB * NT;

    // ---- prologue stage 1 ----
    for (int r = gid; r < 4096; r += gn) {
        int r2 = (r & 1023) * 4 + (r >> 10);
        g_bA[r2] = bih_a[r] + bhh_a[r];
        g_bD[r2] = bih_d[r] + bhh_d[r];
    }
    for (int i = gid; i < BATCH * TENC; i += gn) { g_ctx[i] = 0.f; g_aw[i] = 0.f; g_awt[i] = 0.f; }
    for (int i = gid; i < HDIM * BATCH; i += gn) {
        g_ah[0][i] = 0.f; g_ac[0][i] = 0.f; g_dh[0][i] = 0.f; g_dc[0][i] = 0.f;
    }
    for (int i = gid; i < 128 * 1024; i += gn) {
        int j = i >> 10, k = i & 1023;
        g_wqT[k * 128 + j] = wq[(size_t)j * 1024 + k];
    }
    for (int i = gid; i < 4096; i += gn) { int j = i >> 5, c = i & 31; g_wlp[c * 128 + j] = wl[i]; }
    for (int i = gid; i < 1536 * 176; i += gn) {
        int k = i / 176, j = i % 176;
        float v = (j < 160) ? wm[(size_t)j * 1536 + k] : (j == 160 ? wg[k] : 0.f);
        g_wmT[(size_t)(k >> 2) * 704 + j * 4 + (k & 3)] = v;
    }
    for (int i = gid; i < 176; i += gn) g_bmp[i] = (i < 160) ? bm[i] : (i == 160 ? bg[0] : 0.f);

    tpose(s, g_wAT, wih_a, 768, 0, bi, tid);
    tpose(s, g_wAT, whh_a, 1024, 768, bi, tid);
    tpose(s, g_wDT, wih_d, 1536, 0, bi, tid);
    tpose(s, g_wDT, whh_d, 1024, 1536, bi, tid);

    // prenet layer 1 (1002 chunks of 16 rows)
    for (int it = 0; it < 8; it++) {
        int ch = it * NB + bi;
        int n0 = ch * 16;
        bool ok = ch < 1002;
        __syncthreads();
        if (ok)
            for (int i = tid; i < 16 * NMEL; i += NT) {
                int row = i / NMEL, k = i % NMEL;
                int nn = n0 + row, st = nn >> 5, b = nn & 31;
                s.p1.x[row][k] = (st == 0) ? 0.f : mels[((size_t)b * 500 + (st - 1)) * NMEL + k];
            }
        __syncthreads();
        if (ok) {
            float acc[16];
            float bj = __ldg(&b_pre1[tid]);
#pragma unroll
            for (int r = 0; r < 16; r++) acc[r] = bj;
            const float* wr = w_pre1 + (size_t)tid * NMEL;
            for (int k = 0; k < NMEL; k++) {
                float wv = __ldg(&wr[k]);
#pragma unroll
                for (int r = 0; r < 16; r++) acc[r] += wv * s.p1.x[r][k];
            }
            for (int r = 0; r < 16; r++)
                g_tmp[(size_t)(n0 + r) * PRE + tid] = fmaxf(acc[r], 0.f);
        }
    }
    // keys (2048 chunks of 8 rows -> 16 iters/block)
    for (int it = 0; it < 16; it++) {
        int r0 = (it * NB + bi) * 8;
        __syncthreads();
        for (int i = tid; i < 8 * DENC; i += NT) {
            int row = i >> 9, k = i & 511;
            s.ke.x[row][k] = enc[(size_t)(r0 + row) * DENC + k];
        }
        __syncthreads();
        int j = tid & 127, rh = tid >> 7;
        const float* wr = wk + (size_t)j * DENC;
        float a0 = 0, a1 = 0, a2 = 0, a3 = 0;
        for (int k = 0; k < DENC; k++) {
            float wv = __ldg(&wr[k]);
            a0 += wv * s.ke.x[rh * 4 + 0][k];
            a1 += wv * s.ke.x[rh * 4 + 1][k];
            a2 += wv * s.ke.x[rh * 4 + 2][k];
            a3 += wv * s.ke.x[rh * 4 + 3][k];
        }
        float bkj = __ldg(&bk[j]);
        g_keys[(size_t)(r0 + rh * 4 + 0) * 128 + j] = a0 + bkj;
        g_keys[(size_t)(r0 + rh * 4 + 1) * 128 + j] = a1 + bkj;
        g_keys[(size_t)(r0 + rh * 4 + 2) * 128 + j] = a2 + bkj;
        g_keys[(size_t)(r0 + rh * 4 + 3) * 128 + j] = a3 + bkj;
    }
    gsync();
    // prenet layer 2
    for (int it = 0; it < 8; it++) {
        int ch = it * NB + bi;
        int n0 = ch * 16;
        bool ok = ch < 1002;
        __syncthreads();
        if (ok)
            for (int i = tid; i < 16 * PRE; i += NT) {
                int row = i >> 8, k = i & 255;
                s.p2.x[row][k] = g_tmp[(size_t)(n0 + row) * PRE + k];
            }
        __syncthreads();
        if (ok) {
            float acc[16];
            float bj = __ldg(&b_pre2[tid]);
#pragma unroll
            for (int r = 0; r < 16; r++) acc[r] = bj;
            const float* wr = w_pre2 + (size_t)tid * PRE;
            for (int k = 0; k < PRE; k++) {
                float wv = __ldg(&wr[k]);
#pragma unroll
                for (int r = 0; r < 16; r++) acc[r] += wv * s.p2.x[r][k];
            }
            for (int r = 0; r < 16; r++) {
                int nn = n0 + r, t = nn >> 5, b = nn & 31;
                g_pre[((size_t)t * PRE + tid) * 32 + b] = fmaxf(acc[r], 0.f);
            }
        }
    }
    gsync();

    // ---- main sequential loop: 3 barriers per step ----
    for (int t = 0; t < TSTEPS; t++) {
        if (bi < 32 && t > 0) outproj(s, t - 1, bi, g_dh[t & 1], outM, outG);
        lstm<0>(s, t, bi, tid);
        conv(s, bi, tid, cw, cb, bl);
        gsync();
        if (bi < 32) attn(s, t, bi, tid, enc, bq, wa, ba, mask, outA);
        gsync();
        lstm<1>(s, t, bi, tid);
        gsync();
    }
    if (bi < 32) outproj(s, TSTEPS - 1, bi, g_dh[1], outM, outG);
}

// ---------------- host launch: ONE kernel node ----------------
extern "C" void kernel_launch(void* const* d_in, const int* in_sizes, int n_in,
                              void* d_out, int out_size) {
    (void)in_sizes; (void)n_in; (void)out_size;
    float* out  = (float*)d_out;
    float* outM = out;
    float* outG = out + (size_t)TSTEPS * BATCH * NMEL;
    float* outA = outG + (size_t)TSTEPS * BATCH;
    mega<<<NB, NT>>>(
        (const float*)d_in[0], (const float*)d_in[1], (const unsigned char*)d_in[2],
        (const float*)d_in[3], (const float*)d_in[4], (const float*)d_in[5], (const float*)d_in[6],
        (const float*)d_in[7], (const float*)d_in[8], (const float*)d_in[9], (const float*)d_in[10],
        (const float*)d_in[11], (const float*)d_in[12], (const float*)d_in[13], (const float*)d_in[14],
        (const float*)d_in[15], (const float*)d_in[16], (const float*)d_in[17], (const float*)d_in[18],
        (const float*)d_in[19], (const float*)d_in[20], (const float*)d_in[21], (const float*)d_in[22],
        (const float*)d_in[23], (const float*)d_in[24], (const float*)d_in[25], (const float*)d_in[26],
        (const float*)d_in[27], (const float*)d_in[28],
        outM, outG, outA);
}

// round 17
// speedup vs baseline: 1.0003x; 1.0003x over previous
#include <cuda_runtime.h>
#include <math.h>

#define TSTEPS 501
#define BATCH  32
#define TENC   512
#define DENC   512
#define NMEL   160
#define PRE    256
#define HDIM   1024
#define KA     1792
#define KD     2560
#define NB     128
#define NT     256

// ---------------- static device scratch ----------------
__device__ float g_wAT[KA * 4096];     // k-major, gate-interleaved cols (cell*4+gate)
__device__ float g_wDT[KD * 4096];
__device__ float g_bA[4096], g_bD[4096];          // remapped bias
__device__ float g_wqT[HDIM * 128];               // [k][j]
__device__ float g_wlp[32 * 128];                 // [c][j]
__device__ float g_wmT[384 * 176 * 4];            // [k/4][j(176)][4k]
__device__ float g_bmp[176];
__device__ float g_tmp[TSTEPS * BATCH * PRE];
__device__ float g_pre[TSTEPS * PRE * BATCH];     // [t][k][b]
__device__ float g_keys[BATCH * TENC * 128];
__device__ float g_loc [BATCH * TENC * 128];
__device__ float g_ctx[DENC * BATCH];             // [d][b]
__device__ float g_ah[2][HDIM * BATCH];           // [cell][b]
__device__ float g_ac[2][HDIM * BATCH];
__device__ float g_dh[2][HDIM * BATCH];
__device__ float g_dc[2][HDIM * BATCH];
__device__ float g_aw [BATCH * TENC], g_awt[BATCH * TENC];
__device__ unsigned g_cnt = 0;
__device__ volatile unsigned g_gen = 0;

union Smem {
    float tr[32][33];
    struct { float x[16][NMEL]; } p1;
    struct { float x[16][PRE]; } p2;
    struct { float x[8][DENC]; } ke;
    struct { float xs[2048]; } ls;                      // [kk][b]
    struct { float aw[512], awt[512], slc[128][33]; } cv;
    struct { float sah[1024], sq[128], swa[128], qp[256], e[512], sp[512], red[256]; } at;
    struct { float sh[1536]; } op;
};

__device__ __forceinline__ void gsync() {
    __threadfence();
    __syncthreads();
    if (threadIdx.x == 0) {
        unsigned gen = g_gen;
        if (atomicAdd(&g_cnt, 1u) == NB - 1u) { g_cnt = 0u; __threadfence(); g_gen = gen + 1u; }
        else { while (g_gen == gen) __nanosleep(64); }
    }
    __syncthreads();
    __threadfence();
}

// accurate fast tanh: 1 - 2/(e^{2x}+1); rel err ~1e-6 (vs 1e-3 for tanh.approx)
__device__ __forceinline__ float tnh(float x) {
    float e = __expf(2.f * x);
    return 1.f - __fdividef(2.f, e + 1.f);
}
__device__ __forceinline__ float sigf(float x) { return 1.f / (1.f + expf(-x)); }

// transpose src[4096][C] -> dst[(rowOff+c)*4096 + remap(r)], remap(r)=(r&1023)*4+(r>>10)
__device__ void tpose(Smem& s, float* dst, const float* __restrict__ src,
                      int C, int rowOff, int bi, int tid) {
    int x = tid & 31, y = tid >> 5;
    int ntile = (C >> 5) * 128;
    for (int idx = bi; idx < ntile; idx += NB) {
        int rt = idx & 127, ct = idx >> 7;
        __syncthreads();
#pragma unroll
        for (int i = 0; i < 4; i++)
            s.tr[y + i * 8][x] = src[(size_t)(rt * 32 + y + i * 8) * C + ct * 32 + x];
        __syncthreads();
        int g = (rt * 32) >> 10, rb = ((rt * 32) & 1023) * 4 + g;
#pragma unroll
        for (int i = 0; i < 4; i++) {
            int c = ct * 32 + y + i * 8;
            dst[(size_t)(rowOff + c) * 4096 + rb + x * 4] = s.tr[x][y + i * 8];
        }
    }
    __syncthreads();
}

// ---------------- fused LSTM: warp = 1 cell x 32 batch lanes ----------------
template <int MODE>
__device__ void lstm(Smem& s, int t, int bi, int tid) {
    const int p = t & 1, n = p ^ 1;
    constexpr int K = MODE ? KD : KA;
    const float* wT    = MODE ? g_wDT : g_wAT;
    const float* bias  = MODE ? g_bD  : g_bA;
    const float* cprev = MODE ? g_dc[p] : g_ac[p];
    float* co = MODE ? g_dc[n] : g_ac[n];
    float* ho = MODE ? g_dh[n] : g_ah[n];
    const float* ahr = MODE ? g_ah[n] : g_ah[p];
    const float* dhr = g_dh[p];
    const float* pret = g_pre + (size_t)t * PRE * BATCH;

    int lane = tid & 31, w = tid >> 5;
    int cell = bi * 8 + w;
    float4 bs = *(const float4*)&bias[cell * 4];
    unsigned long long a01, a23;
    asm("mov.b64 %0,{%1,%2};" : "=l"(a01) : "f"(bs.x), "f"(bs.y));
    asm("mov.b64 %0,{%1,%2};" : "=l"(a23) : "f"(bs.z), "f"(bs.w));

    for (int kt = 0; kt < K / 64; kt++) {
        __syncthreads();
#pragma unroll
        for (int i = 0; i < 8; i++) {
            int idx = i * NT + tid;
            int kk = idx >> 5, b = idx & 31;
            int kg = kt * 64 + kk;
            float v;
            if (MODE == 0)
                v = kg < 256 ? pret[kg * 32 + b]
                  : (kg < 768 ? __ldcg(&g_ctx[(kg - 256) * 32 + b])
                              : __ldcg(&ahr[(kg - 768) * 32 + b]));
            else
                v = kg < 512 ? __ldcg(&g_ctx[kg * 32 + b])
                  : (kg < 1536 ? __ldcg(&ahr[(kg - 512) * 32 + b])
                               : __ldcg(&dhr[(kg - 1536) * 32 + b]));
            s.ls.xs[idx] = v;
        }
        __syncthreads();
        const float* wb = wT + (size_t)(kt * 64) * 4096 + cell * 4;
#pragma unroll 8
        for (int kk = 0; kk < 64; kk++) {
            ulonglong2 wv = __ldg((const ulonglong2*)(wb + (size_t)kk * 4096));
            float x = s.ls.xs[kk * 32 + lane];
            unsigned long long x2;
            asm("mov.b64 %0,{%1,%1};" : "=l"(x2) : "f"(x));
            asm("fma.rn.f32x2 %0,%1,%2,%0;" : "+l"(a01) : "l"(wv.x), "l"(x2));
            asm("fma.rn.f32x2 %0,%1,%2,%0;" : "+l"(a23) : "l"(wv.y), "l"(x2));
        }
    }
    float gi, gf, gg, go;
    asm("mov.b64 {%0,%1},%2;" : "=f"(gi), "=f"(gf) : "l"(a01));
    asm("mov.b64 {%0,%1},%2;" : "=f"(gg), "=f"(go) : "l"(a23));
    float cp = cprev[cell * 32 + lane];
    float cn = sigf(gf) * cp + sigf(gi) * tanhf(gg);
    co[cell * 32 + lane] = cn;
    ho[cell * 32 + lane] = sigf(go) * tanhf(cn);
    __syncthreads();
}

// ---------------- location conv + projection ----------------
__device__ void conv(Smem& s, int bi, int tid, const float* __restrict__ cw,
                     const float* __restrict__ cb, const float* __restrict__ bl) {
    int b = bi >> 2, t0 = (bi & 3) * 128;
    __syncthreads();
    for (int i = tid; i < 512; i += NT) {
        s.cv.aw[i]  = __ldcg(&g_aw[b * 512 + i]);
        s.cv.awt[i] = __ldcg(&g_awt[b * 512 + i]);
    }
    __syncthreads();
    if (tid < 128) {
        int tg = t0 + tid;
        float lc[32];
#pragma unroll
        for (int c = 0; c < 32; c++) lc[c] = __ldg(&cb[c]);
        for (int k = 0; k < 31; k++) {
            int tt = tg - 15 + k;
            if (tt >= 0 && tt < 512) {
                float av = s.cv.aw[tt], wv = s.cv.awt[tt];
#pragma unroll
                for (int c = 0; c < 32; c++)
                    lc[c] += __ldg(&cw[c * 62 + k]) * av + __ldg(&cw[c * 62 + 31 + k]) * wv;
            }
        }
#pragma unroll
        for (int c = 0; c < 32; c++) s.cv.slc[tid][c] = lc[c];
    }
    __syncthreads();
    int j = tid & 127, th = tid >> 7;
    float wreg[32];
#pragma unroll
    for (int c = 0; c < 32; c++) wreg[c] = __ldg(&g_wlp[c * 128 + j]);
    float blv = __ldg(&bl[j]);
    for (int ti = 0; ti < 64; ti++) {
        int tl = th * 64 + ti;
        float acc = blv;
#pragma unroll
        for (int c = 0; c < 32; c++) acc += wreg[c] * s.cv.slc[tl][c];
        g_loc[((size_t)(b * 512 + t0 + tl)) * 128 + j] = acc;
    }
    __syncthreads();
}

// ---------------- output projection for step 'to' ----------------
__device__ void outproj(Smem& s, int to, int b, const float* __restrict__ dhp,
                        float* __restrict__ outM, float* __restrict__ outG) {
    int tid = threadIdx.x;
    __syncthreads();
    for (int i = tid; i < 1536; i += NT)
        s.op.sh[i] = (i < 1024) ? __ldcg(&dhp[i * 32 + b]) : __ldcg(&g_ctx[(i - 1024) * 32 + b]);
    __syncthreads();
    if (tid < 176) {
        float acc = g_bmp[tid];
        for (int k4 = 0; k4 < 384; k4++) {
            float4 w = *(const float4*)&g_wmT[(size_t)k4 * 704 + tid * 4];
            float4 x = *(const float4*)&s.op.sh[k4 * 4];
            acc += w.x * x.x + w.y * x.y + w.z * x.z + w.w * x.w;
        }
        if (tid < 160) outM[((size_t)to * BATCH + b) * NMEL + tid] = acc;
        else if (tid == 160) outG[(size_t)to * BATCH + b] = acc;
    }
    __syncthreads();
}

// ---------------- attention ----------------
__device__ void attn(Smem& s, int t, int b, int tid, const float* __restrict__ enc,
                     const float* __restrict__ bq, const float* __restrict__ wa,
                     const float* __restrict__ ba, const unsigned char* __restrict__ mask,
                     float* __restrict__ outA) {
    const int n = (t & 1) ^ 1;
    __syncthreads();
    for (int i = tid; i < 1024; i += NT) s.at.sah[i] = __ldcg(&g_ah[n][i * 32 + b]);
    if (tid < 128) s.at.swa[tid] = __ldg(&wa[tid]);
    __syncthreads();
    {
        int j = tid & 127, h = tid >> 7;
        float acc = 0.f;
        const float* wr = &g_wqT[(size_t)(h * 512) * 128 + j];
        const float* xr = &s.at.sah[h * 512];
#pragma unroll 8
        for (int k = 0; k < 512; k++) acc += __ldg(wr + (size_t)k * 128) * xr[k];
        s.at.qp[tid] = acc;
    }
    __syncthreads();
    if (tid < 128) s.at.sq[tid] = __ldg(&bq[tid]) + s.at.qp[tid] + s.at.qp[tid + 128];
    __syncthreads();

    float bav = __ldg(&ba[0]);
#pragma unroll
    for (int i = 0; i < 2; i++) {
        int tt = i * 256 + tid;
        const float4* kp = (const float4*)&g_keys[(size_t)(b * 512 + tt) * 128];
        const float4* lp = (const float4*)&g_loc [(size_t)(b * 512 + tt) * 128];
        float ee = bav;
#pragma unroll 4
        for (int j4 = 0; j4 < 32; j4++) {
            float4 q = *(const float4*)&s.at.sq[j4 * 4];
            float4 w = *(const float4*)&s.at.swa[j4 * 4];
            float4 kv = __ldcg(&kp[j4]);
            float4 lv = __ldcg(&lp[j4]);
            ee += w.x * tnh(q.x + kv.x + lv.x) + w.y * tnh(q.y + kv.y + lv.y)
                + w.z * tnh(q.z + kv.z + lv.z) + w.w * tnh(q.w + kv.w + lv.w);
        }
        if (mask[b * 512 + tt]) ee = -INFINITY;
        s.at.e[tt] = ee;
    }
    __syncthreads();
    s.at.red[tid] = fmaxf(s.at.e[tid], s.at.e[256 + tid]);
    __syncthreads();
    for (int st = 128; st > 0; st >>= 1) {
        if (tid < st) s.at.red[tid] = fmaxf(s.at.red[tid], s.at.red[tid + st]);
        __syncthreads();
    }
    float mx = s.at.red[0];
    __syncthreads();
    float ls = 0.f;
#pragma unroll
    for (int i = 0; i < 2; i++) {
        int tt = i * 256 + tid;
        float pv = expf(s.at.e[tt] - mx);
        s.at.sp[tt] = pv; ls += pv;
    }
    s.at.red[tid] = ls;
    __syncthreads();
    for (int st = 128; st > 0; st >>= 1) {
        if (tid < st) s.at.red[tid] += s.at.red[tid + st];
        __syncthreads();
    }
    float inv = 1.f / s.at.red[0];
    __syncthreads();
#pragma unroll
    for (int i = 0; i < 2; i++) {
        int tt = i * 256 + tid;
        float pv = s.at.sp[tt] * inv;
        s.at.sp[tt] = pv;
        g_aw[b * 512 + tt] = pv;
        g_awt[b * 512 + tt] += pv;
        outA[((size_t)t * BATCH + b) * 512 + tt] = pv;
    }
    __syncthreads();
#pragma unroll
    for (int i = 0; i < 2; i++) {
        int d = i * 256 + tid;
        const float* eb = enc + (size_t)b * 512 * 512 + d;
        float acc = 0.f;
#pragma unroll 8
        for (int tt = 0; tt < 512; tt++) acc += s.at.sp[tt] * __ldg(eb + (size_t)tt * 512);
        g_ctx[d * 32 + b] = acc;
    }
    __syncthreads();
}

// ---------------- the single persistent kernel ----------------
__global__ void __launch_bounds__(NT, 1) mega(
    const float* __restrict__ enc, const float* __restrict__ mels,
    const unsigned char* __restrict__ mask,
    const float* __restrict__ w_pre1, const float* __restrict__ b_pre1,
    const float* __restrict__ w_pre2, const float* __restrict__ b_pre2,
    const float* __restrict__ wih_a, const float* __restrict__ whh_a,
    const float* __restrict__ bih_a, const float* __restrict__ bhh_a,
    const float* __restrict__ wq, const float* __restrict__ bq,
    const float* __restrict__ wk, const float* __restrict__ bk,
    const float* __restrict__ cw, const float* __restrict__ cb,
    const float* __restrict__ wl, const float* __restrict__ bl,
    const float* __restrict__ wa, const float* __restrict__ ba,
    const float* __restrict__ wih_d, const float* __restrict__ whh_d,
    const float* __restrict__ bih_d, const float* __restrict__ bhh_d,
    const float* __restrict__ wm, const float* __restrict__ bm,
    const float* __restrict__ wg, const float* __restrict__ bg,
    float* __restrict__ outM, float* __restrict__ outG, float* __restrict__ outA)
{
    __shared__ Smem s;
    int bi = blockIdx.x, tid = threadIdx.x;
    int gid = bi * NT + tid, gn = NB * NT;

    // ---- prologue stage 1 ----
    for (int r = gid; r < 4096; r += gn) {
        int r2 = (r & 1023) * 4 + (r >> 10);
        g_bA[r2] = bih_a[r] + bhh_a[r];
        g_bD[r2] = bih_d[r] + bhh_d[r];
    }
    for (int i = gid; i < BATCH * TENC; i += gn) { g_ctx[i] = 0.f; g_aw[i] = 0.f; g_awt[i] = 0.f; }
    for (int i = gid; i < HDIM * BATCH; i += gn) {
        g_ah[0][i] = 0.f; g_ac[0][i] = 0.f; g_dh[0][i] = 0.f; g_dc[0][i] = 0.f;
    }
    for (int i = gid; i < 128 * 1024; i += gn) {
        int j = i >> 10, k = i & 1023;
        g_wqT[k * 128 + j] = wq[(size_t)j * 1024 + k];
    }
    for (int i = gid; i < 4096; i += gn) { int j = i >> 5, c = i & 31; g_wlp[c * 128 + j] = wl[i]; }
    for (int i = gid; i < 1536 * 176; i += gn) {
        int k = i / 176, j = i % 176;
        float v = (j < 160) ? wm[(size_t)j * 1536 + k] : (j == 160 ? wg[k] : 0.f);
        g_wmT[(size_t)(k >> 2) * 704 + j * 4 + (k & 3)] = v;
    }
    for (int i = gid; i < 176; i += gn) g_bmp[i] = (i < 160) ? bm[i] : (i == 160 ? bg[0] : 0.f);

    tpose(s, g_wAT, wih_a, 768, 0, bi, tid);
    tpose(s, g_wAT, whh_a, 1024, 768, bi, tid);
    tpose(s, g_wDT, wih_d, 1536, 0, bi, tid);
    tpose(s, g_wDT, whh_d, 1024, 1536, bi, tid);

    // prenet layer 1 (1002 chunks of 16 rows)
    for (int it = 0; it < 8; it++) {
        int ch = it * NB + bi;
        int n0 = ch * 16;
        bool ok = ch < 1002;
        __syncthreads();
        if (ok)
            for (int i = tid; i < 16 * NMEL; i += NT) {
                int row = i / NMEL, k = i % NMEL;
                int nn = n0 + row, st = nn >> 5, b = nn & 31;
                s.p1.x[row][k] = (st == 0) ? 0.f : mels[((size_t)b * 500 + (st - 1)) * NMEL + k];
            }
        __syncthreads();
        if (ok) {
            float acc[16];
            float bj = __ldg(&b_pre1[tid]);
#pragma unroll
            for (int r = 0; r < 16; r++) acc[r] = bj;
            const float* wr = w_pre1 + (size_t)tid * NMEL;
            for (int k = 0; k < NMEL; k++) {
                float wv = __ldg(&wr[k]);
#pragma unroll
                for (int r = 0; r < 16; r++) acc[r] += wv * s.p1.x[r][k];
            }
            for (int r = 0; r < 16; r++)
                g_tmp[(size_t)(n0 + r) * PRE + tid] = fmaxf(acc[r], 0.f);
        }
    }
    // keys (2048 chunks of 8 rows -> 16 iters/block)
    for (int it = 0; it < 16; it++) {
        int r0 = (it * NB + bi) * 8;
        __syncthreads();
        for (int i = tid; i < 8 * DENC; i += NT) {
            int row = i >> 9, k = i & 511;
            s.ke.x[row][k] = enc[(size_t)(r0 + row) * DENC + k];
        }
        __syncthreads();
        int j = tid & 127, rh = tid >> 7;
        const float* wr = wk + (size_t)j * DENC;
        float a0 = 0, a1 = 0, a2 = 0, a3 = 0;
        for (int k = 0; k < DENC; k++) {
            float wv = __ldg(&wr[k]);
            a0 += wv * s.ke.x[rh * 4 + 0][k];
            a1 += wv * s.ke.x[rh * 4 + 1][k];
            a2 += wv * s.ke.x[rh * 4 + 2][k];
            a3 += wv * s.ke.x[rh * 4 + 3][k];
        }
        float bkj = __ldg(&bk[j]);
        g_keys[(size_t)(r0 + rh * 4 + 0) * 128 + j] = a0 + bkj;
        g_keys[(size_t)(r0 + rh * 4 + 1) * 128 + j] = a1 + bkj;
        g_keys[(size_t)(r0 + rh * 4 + 2) * 128 + j] = a2 + bkj;
        g_keys[(size_t)(r0 + rh * 4 + 3) * 128 + j] = a3 + bkj;
    }
    gsync();
    // prenet layer 2
    for (int it = 0; it < 8; it++) {
        int ch = it * NB + bi;
        int n0 = ch * 16;
        bool ok = ch < 1002;
        __syncthreads();
        if (ok)
            for (int i = tid; i < 16 * PRE; i += NT) {
                int row = i >> 8, k = i & 255;
                s.p2.x[row][k] = g_tmp[(size_t)(n0 + row) * PRE + k];
            }
        __syncthreads();
        if (ok) {
            float acc[16];
            float bj = __ldg(&b_pre2[tid]);
#pragma unroll
            for (int r = 0; r < 16; r++) acc[r] = bj;
            const float* wr = w_pre2 + (size_t)tid * PRE;
            for (int k = 0; k < PRE; k++) {
                float wv = __ldg(&wr[k]);
#pragma unroll
                for (int r = 0; r < 16; r++) acc[r] += wv * s.p2.x[r][k];
            }
            for (int r = 0; r < 16; r++) {
                int nn = n0 + r, t = nn >> 5, b = nn & 31;
                g_pre[((size_t)t * PRE + tid) * 32 + b] = fmaxf(acc[r], 0.f);
            }
        }
    }
    gsync();

    // ---- main sequential loop: 3 barriers per step ----
    for (int t = 0; t < TSTEPS; t++) {
        if (bi < 32 && t > 0) outproj(s, t - 1, bi, g_dh[t & 1], outM, outG);
        lstm<0>(s, t, bi, tid);
        conv(s, bi, tid, cw, cb, bl);
        gsync();
        if (bi < 32) attn(s, t, bi, tid, enc, bq, wa, ba, mask, outA);
        gsync();
        lstm<1>(s, t, bi, tid);
        gsync();
    }
    if (bi < 32) outproj(s, TSTEPS - 1, bi, g_dh[1], outM, outG);
}

// ---------------- host launch: ONE kernel node ----------------
extern "C" void kernel_launch(void* const* d_in, const int* in_sizes, int n_in,
                              void* d_out, int out_size) {
    (void)in_sizes; (void)n_in; (void)out_size;
    float* out  = (float*)d_out;
    float* outM = out;
    float* outG = out + (size_t)TSTEPS * BATCH * NMEL;
    float* outA = outG + (size_t)TSTEPS * BATCH;
    mega<<<NB, NT>>>(
        (const float*)d_in[0], (const float*)d_in[1], (const unsigned char*)d_in[2],
        (const float*)d_in[3], (const float*)d_in[4], (const float*)d_in[5], (const float*)d_in[6],
        (const float*)d_in[7], (const float*)d_in[8], (const float*)d_in[9], (const float*)d_in[10],
        (const float*)d_in[11], (const float*)d_in[12], (const float*)d_in[13], (const float*)d_in[14],
        (const float*)d_in[15], (const float*)d_in[16], (const float*)d_in[17], (const float*)d_in[18],
        (const float*)d_in[19], (const float*)d_in[20], (const float*)d_in[21], (const float*)d_in[22],
        (const float*)d_in[23], (const float*)d_in[24], (const float*)d_in[25], (const float*)d_in[26],
        (const float*)d_in[27], (const float*)d_in[28],
        outM, outG, outA);
}